// round 1
// baseline (speedup 1.0000x reference)
#include <cuda_runtime.h>
#include <cuda_bf16.h>

// Problem constants (fixed by the reference)
#define T_TOK   8192          // B*S tokens
#define HID     1024
#define EXD     3072
#define NEXP    8
#define TOPK    2
#define NROUTE  (T_TOK * TOPK)        // 16384

// GEMM tiling
#define BM 64
#define BN 64
#define BK 16
#define MAX_ROWS  (NROUTE + NEXP * BM)   // 16896 (per-expert padding to BM)
#define MAX_TILES (MAX_ROWS / BM)        // 264

// -------- device scratch (static; no allocation allowed) --------
__device__ int   g_cnt[NEXP];
__device__ int   g_fill[NEXP];
__device__ int   g_tile_expert[MAX_TILES];
__device__ int   g_num_tiles;
__device__ int   g_route_token[MAX_ROWS];       // -1 for padding rows
__device__ int   g_route_pos[NROUTE];           // (t,k) -> padded route row
__device__ float g_H[(size_t)MAX_ROWS * EXD];   // ~208 MB intermediate
__device__ float g_Y[(size_t)MAX_ROWS * HID];   // ~69 MB per-route output

// -------- routing kernels --------
__global__ void k_init() {
    int i = blockIdx.x * blockDim.x + threadIdx.x;
    if (i < MAX_ROWS) g_route_token[i] = -1;
    if (i < NEXP)     g_cnt[i] = 0;
}

__global__ void k_count(const int* __restrict__ idx) {
    int i = blockIdx.x * blockDim.x + threadIdx.x;
    if (i < NROUTE) atomicAdd(&g_cnt[idx[i]], 1);
}

__global__ void k_offsets() {
    if (threadIdx.x != 0 || blockIdx.x != 0) return;
    int off = 0, tile = 0;
    for (int e = 0; e < NEXP; e++) {
        g_fill[e] = off;
        int tiles_e = (g_cnt[e] + BM - 1) / BM;
        for (int t = 0; t < tiles_e; t++) g_tile_expert[tile++] = e;
        off += tiles_e * BM;
    }
    g_num_tiles = tile;
}

__global__ void k_scatter(const int* __restrict__ idx) {
    int i = blockIdx.x * blockDim.x + threadIdx.x;
    if (i >= NROUTE) return;
    int e = idx[i];
    int pos = atomicAdd(&g_fill[e], 1);
    g_route_token[pos] = i / TOPK;
    g_route_pos[i] = pos;
}

// -------- shared 64x64x16 fp32 GEMM body --------
// C[row, n] = sum_k A(row)[k] * W_e[k, n]; row tiles grouped by expert.
template <bool GATHER>
__device__ __forceinline__ void gemm_body(
    const float* __restrict__ A,      // GATHER: x [T,HID] ; else g_H [MAX_ROWS,Kd]
    const float* __restrict__ W,      // [NEXP, Kd, Nd]
    float* __restrict__ C,            // [MAX_ROWS, Nd]
    int Kd, int Nd)
{
    int tile = blockIdx.y;
    if (tile >= g_num_tiles) return;
    int e = g_tile_expert[tile];
    const float* B = W + (size_t)e * Kd * Nd;
    int row0 = tile * BM;
    int n0   = blockIdx.x * BN;

    __shared__ float As[BK][BM + 4];
    __shared__ float Bs[BK][BN];

    int tid = threadIdx.x;

    // A tile load: each thread one float4. ra = row-in-tile, ka = k offset.
    int ra = tid >> 2;
    int ka = (tid & 3) * 4;
    const float* Aptr;
    if (GATHER) {
        int tok = g_route_token[row0 + ra];
        Aptr = (tok >= 0) ? (A + (size_t)tok * Kd + ka) : nullptr;
    } else {
        Aptr = A + (size_t)(row0 + ra) * Kd + ka;
    }

    // B tile load: kb = k row, nb = n offset
    int kb = tid >> 4;
    int nb = (tid & 15) * 4;
    const float* Bptr = B + (size_t)kb * Nd + n0 + nb;

    int tx = tid & 15, ty = tid >> 4;
    float acc[4][4];
    #pragma unroll
    for (int i = 0; i < 4; i++)
        #pragma unroll
        for (int j = 0; j < 4; j++) acc[i][j] = 0.f;

    for (int k0 = 0; k0 < Kd; k0 += BK) {
        float4 av = make_float4(0.f, 0.f, 0.f, 0.f);
        if (Aptr) av = *(const float4*)(Aptr + k0);
        float4 bv = *(const float4*)(Bptr + (size_t)k0 * Nd);

        __syncthreads();
        As[ka + 0][ra] = av.x;
        As[ka + 1][ra] = av.y;
        As[ka + 2][ra] = av.z;
        As[ka + 3][ra] = av.w;
        *(float4*)&Bs[kb][nb] = bv;
        __syncthreads();

        #pragma unroll
        for (int kk = 0; kk < BK; kk++) {
            float4 a4 = *(const float4*)&As[kk][ty * 4];
            float4 b4 = *(const float4*)&Bs[kk][tx * 4];
            acc[0][0] += a4.x * b4.x; acc[0][1] += a4.x * b4.y;
            acc[0][2] += a4.x * b4.z; acc[0][3] += a4.x * b4.w;
            acc[1][0] += a4.y * b4.x; acc[1][1] += a4.y * b4.y;
            acc[1][2] += a4.y * b4.z; acc[1][3] += a4.y * b4.w;
            acc[2][0] += a4.z * b4.x; acc[2][1] += a4.z * b4.y;
            acc[2][2] += a4.z * b4.z; acc[2][3] += a4.z * b4.w;
            acc[3][0] += a4.w * b4.x; acc[3][1] += a4.w * b4.y;
            acc[3][2] += a4.w * b4.z; acc[3][3] += a4.w * b4.w;
        }
    }

    #pragma unroll
    for (int i = 0; i < 4; i++) {
        float* cp = C + (size_t)(row0 + ty * 4 + i) * Nd + n0 + tx * 4;
        *(float4*)cp = make_float4(acc[i][0], acc[i][1], acc[i][2], acc[i][3]);
    }
}

__global__ __launch_bounds__(256)
void k_gemm1(const float* __restrict__ x, const float* __restrict__ up) {
    gemm_body<true>(x, up, g_H, HID, EXD);
}

__global__ __launch_bounds__(256)
void k_gemm2(const float* __restrict__ down) {
    gemm_body<false>(g_H, down, g_Y, EXD, HID);
}

// -------- deterministic combine: out[t] = w0*Y[pos0] + w1*Y[pos1] --------
__global__ void k_combine(const float* __restrict__ ew, float* __restrict__ out) {
    int i = blockIdx.x * blockDim.x + threadIdx.x;
    if (i >= T_TOK * HID) return;
    int t = i >> 10;          // /HID
    int h = i & (HID - 1);
    int p0 = g_route_pos[t * TOPK + 0];
    int p1 = g_route_pos[t * TOPK + 1];
    float w0 = ew[t * TOPK + 0];
    float w1 = ew[t * TOPK + 1];
    out[i] = w0 * g_Y[(size_t)p0 * HID + h] + w1 * g_Y[(size_t)p1 * HID + h];
}

extern "C" void kernel_launch(void* const* d_in, const int* in_sizes, int n_in,
                              void* d_out, int out_size) {
    const float* x    = (const float*)d_in[0];
    const int*   idx  = (const int*)  d_in[1];
    const float* ew   = (const float*)d_in[2];
    const float* up   = (const float*)d_in[3];
    const float* down = (const float*)d_in[4];
    float* out = (float*)d_out;

    k_init   <<<(MAX_ROWS + 255) / 256, 256>>>();
    k_count  <<<(NROUTE + 255) / 256, 256>>>(idx);
    k_offsets<<<1, 32>>>();
    k_scatter<<<(NROUTE + 255) / 256, 256>>>(idx);

    k_gemm1<<<dim3(EXD / BN, MAX_TILES), 256>>>(x, up);
    k_gemm2<<<dim3(HID / BN, MAX_TILES), 256>>>(down);

    k_combine<<<(T_TOK * HID + 255) / 256, 256>>>(ew, out);
}

// round 8
// speedup vs baseline: 2.4505x; 2.4505x over previous
#include <cuda_runtime.h>
#include <cuda_bf16.h>
#include <cstdint>

// ---------------- problem constants ----------------
#define T_TOK   8192
#define HID     1024
#define EXD     3072
#define NEXP    8
#define TOPK    2
#define NROUTE  (T_TOK * TOPK)          // 16384
#define BM      128
#define MAX_ROWS (NROUTE + NEXP * BM)   // 17408
#define MAX_MT   (MAX_ROWS / BM)        // 136
#define KCHUNK  1024                    // H column chunk (3 chunks of EXD)

// ---------------- GEMM tile config ----------------
#define TILE_N   128
#define BK       32
#define NSTAGE   3
#define A_HI     0
#define A_LO     8192
#define B_HI     16384
#define B_LO     24576
#define STAGE_BYTES 32768
#define SMEM_BYTES (NSTAGE * STAGE_BYTES)

// ---------------- device scratch (static; ~239 MB total) ----------------
__device__ int g_cnt[NEXP];
__device__ int g_fill[NEXP];
__device__ int g_tile_expert[MAX_MT];
__device__ int g_num_tiles;
__device__ int g_route_token[MAX_ROWS];
__device__ int g_route_pos[NROUTE];

__device__ __align__(256) __nv_bfloat16 g_Ahi [(size_t)MAX_ROWS * HID];    // 35.7 MB
__device__ __align__(256) __nv_bfloat16 g_Alo [(size_t)MAX_ROWS * HID];    // 35.7 MB
__device__ __align__(256) __nv_bfloat16 g_W1hi[(size_t)EXD * HID];         // 6.3 MB  [n][k]
__device__ __align__(256) __nv_bfloat16 g_W1lo[(size_t)EXD * HID];
__device__ __align__(256) __nv_bfloat16 g_W2hi[(size_t)HID * EXD];         // 6.3 MB  [n][k]
__device__ __align__(256) __nv_bfloat16 g_W2lo[(size_t)HID * EXD];
__device__ __align__(256) __nv_bfloat16 g_Hchi[(size_t)MAX_ROWS * KCHUNK]; // 35.7 MB
__device__ __align__(256) __nv_bfloat16 g_Hclo[(size_t)MAX_ROWS * KCHUNK]; // 35.7 MB
__device__ __align__(256) float         g_Y   [(size_t)MAX_ROWS * HID];    // 71.3 MB

// ---------------- PTX helpers ----------------
__device__ __forceinline__ uint32_t smem_u32(const void* p) {
    uint32_t a;
    asm("{ .reg .u64 t; cvta.to.shared.u64 t, %1; cvt.u32.u64 %0, t; }" : "=r"(a) : "l"(p));
    return a;
}
__device__ __forceinline__ void cpa16(uint32_t dst, const void* src) {
    asm volatile("cp.async.cg.shared.global [%0], [%1], 16;" :: "r"(dst), "l"(src));
}
__device__ __forceinline__ void cp_commit() { asm volatile("cp.async.commit_group;" ::: "memory"); }
template <int N>
__device__ __forceinline__ void cp_wait() { asm volatile("cp.async.wait_group %0;" :: "n"(N) : "memory"); }

#define LDSM4(d, addr) \
    asm volatile("ldmatrix.sync.aligned.m8n8.x4.shared.b16 {%0,%1,%2,%3}, [%4];" \
        : "=r"((d)[0]), "=r"((d)[1]), "=r"((d)[2]), "=r"((d)[3]) : "r"(addr))

#define MMA(c, a, b0, b1) \
    asm volatile("mma.sync.aligned.m16n8k16.row.col.f32.bf16.bf16.f32 " \
        "{%0,%1,%2,%3}, {%4,%5,%6,%7}, {%8,%9}, {%0,%1,%2,%3};" \
        : "+f"((c)[0]), "+f"((c)[1]), "+f"((c)[2]), "+f"((c)[3]) \
        : "r"((a)[0]), "r"((a)[1]), "r"((a)[2]), "r"((a)[3]), "r"(b0), "r"(b1))

// swizzled smem offset: row stride 64B, 4 chunks of 16B, chunk ^= (row>>1)&3
__device__ __forceinline__ uint32_t swz(int r, int c) {
    return (uint32_t)(r * 64 + ((c ^ ((r >> 1) & 3)) << 4));
}

// ---------------- routing ----------------
__global__ void k_init() {
    int i = blockIdx.x * blockDim.x + threadIdx.x;
    if (i < MAX_ROWS) g_route_token[i] = -1;
    if (i < NEXP)     g_cnt[i] = 0;
}
__global__ void k_count(const int* __restrict__ idx) {
    int i = blockIdx.x * blockDim.x + threadIdx.x;
    if (i < NROUTE) atomicAdd(&g_cnt[idx[i]], 1);
}
__global__ void k_offsets() {
    if (threadIdx.x != 0 || blockIdx.x != 0) return;
    int off = 0, tile = 0;
    for (int e = 0; e < NEXP; e++) {
        g_fill[e] = off;
        int te = (g_cnt[e] + BM - 1) / BM;
        for (int t = 0; t < te; t++) g_tile_expert[tile++] = e;
        off += te * BM;
    }
    g_num_tiles = tile;
}
__global__ void k_scatter(const int* __restrict__ idx) {
    int i = blockIdx.x * blockDim.x + threadIdx.x;
    if (i >= NROUTE) return;
    int pos = atomicAdd(&g_fill[idx[i]], 1);
    g_route_token[pos] = i / TOPK;
    g_route_pos[i] = pos;
}

// ---------------- fp32 -> bf16 hi/lo ----------------
__device__ __forceinline__ void split1(float v, __nv_bfloat16& h, __nv_bfloat16& l) {
    h = __float2bfloat16(v);
    l = __float2bfloat16(v - __bfloat162float(h));
}

__global__ void k_convert_x(const float* __restrict__ x) {
    int r = blockIdx.x, t = threadIdx.x;
    int tok = g_route_token[r];
    float4 v = make_float4(0.f, 0.f, 0.f, 0.f);
    if (tok >= 0) v = ((const float4*)(x + (size_t)tok * HID))[t];
    __nv_bfloat16 h0,h1,h2,h3,l0,l1,l2,l3;
    split1(v.x,h0,l0); split1(v.y,h1,l1); split1(v.z,h2,l2); split1(v.w,h3,l3);
    __nv_bfloat162 H0; H0.x=h0; H0.y=h1;  __nv_bfloat162 H1; H1.x=h2; H1.y=h3;
    __nv_bfloat162 L0; L0.x=l0; L0.y=l1;  __nv_bfloat162 L1; L1.x=l2; L1.y=l3;
    __nv_bfloat162* ph = (__nv_bfloat162*)(g_Ahi + (size_t)r * HID);
    __nv_bfloat162* pl = (__nv_bfloat162*)(g_Alo + (size_t)r * HID);
    ph[2*t] = H0; ph[2*t+1] = H1;
    pl[2*t] = L0; pl[2*t+1] = L1;
}

// transpose [K][N] fp32 -> [N][K] bf16 hi/lo (32x32 tiles), single expert slice
template <int K, int N>
__device__ __forceinline__ void convert_w_body(const float* __restrict__ w,
                                               __nv_bfloat16* __restrict__ Thi,
                                               __nv_bfloat16* __restrict__ Tlo) {
    __shared__ float s[32][33];
    int n0 = blockIdx.x * 32, k0 = blockIdx.y * 32;
    int tx = threadIdx.x, ty = threadIdx.y;     // (32, 8)
    #pragma unroll
    for (int i = 0; i < 4; i++)
        s[ty + 8 * i][tx] = w[(size_t)(k0 + ty + 8 * i) * N + n0 + tx];
    __syncthreads();
    #pragma unroll
    for (int i = 0; i < 4; i++) {
        int n = n0 + ty + 8 * i, k = k0 + tx;
        float v = s[tx][ty + 8 * i];
        __nv_bfloat16 h, l; split1(v, h, l);
        size_t off = (size_t)n * K + k;
        Thi[off] = h; Tlo[off] = l;
    }
}
__global__ void k_convert_w1(const float* __restrict__ w) {
    convert_w_body<HID, EXD>(w, g_W1hi, g_W1lo);
}
__global__ void k_convert_w2(const float* __restrict__ w) {
    convert_w_body<EXD, HID>(w, g_W2hi, g_W2lo);
}

// ---------------- stage loader (32KB per stage) ----------------
__device__ __forceinline__ void load_stage(uint32_t stage_sb, int tid,
    const __nv_bfloat16* __restrict__ aHi, const __nv_bfloat16* __restrict__ aLo,
    const __nv_bfloat16* __restrict__ bHi, const __nv_bfloat16* __restrict__ bLo,
    int lda, int ldb, int k0)
{
    #pragma unroll
    for (int j = 0; j < 4; j++) {          // A: 2 splits x 128 rows x 4 chunks
        int id = tid + j * 256;
        int split = id >> 9, rem = id & 511;
        int r = rem >> 2, c = rem & 3;
        const __nv_bfloat16* src = (split ? aLo : aHi) + (size_t)r * lda + k0 + c * 8;
        cpa16(stage_sb + (split ? A_LO : A_HI) + swz(r, c), src);
    }
    #pragma unroll
    for (int j = 0; j < 4; j++) {          // B
        int id = tid + j * 256;
        int split = id >> 9, rem = id & 511;
        int r = rem >> 2, c = rem & 3;
        const __nv_bfloat16* src = (split ? bLo : bHi) + (size_t)r * ldb + k0 + c * 8;
        cpa16(stage_sb + (split ? B_LO : B_HI) + swz(r, c), src);
    }
}

// ---------------- grouped bf16 3-MMA GEMM body (K = 1024 fixed) ----------------
template <int LDA, int LDB, int ND, bool SPLIT_OUT>
__device__ __forceinline__ void gemm_body(
    const __nv_bfloat16* __restrict__ aHi, const __nv_bfloat16* __restrict__ aLo,
    const __nv_bfloat16* __restrict__ bHi, const __nv_bfloat16* __restrict__ bLo,
    __nv_bfloat16* __restrict__ Chi, __nv_bfloat16* __restrict__ Clo,
    float* __restrict__ Cf, int row0, int n0, int accum)
{
    extern __shared__ __align__(1024) char smem[];
    uint32_t sb = smem_u32(smem);
    int tid = threadIdx.x, wid = tid >> 5, lane = tid & 31;
    int wm = (wid & 3) * 32;       // warp m-offset (4 warps x 32 rows)
    int wn = (wid >> 2) * 64;      // warp n-offset (2 warps x 64 cols)

    float acc[2][8][4];
    #pragma unroll
    for (int mi = 0; mi < 2; mi++)
        #pragma unroll
        for (int nf = 0; nf < 8; nf++)
            #pragma unroll
            for (int c = 0; c < 4; c++) acc[mi][nf][c] = 0.f;

    constexpr int NCH = 1024 / BK;   // 32
    load_stage(sb, tid, aHi, aLo, bHi, bLo, LDA, LDB, 0);
    cp_commit();
    load_stage(sb + STAGE_BYTES, tid, aHi, aLo, bHi, bLo, LDA, LDB, BK);
    cp_commit();

    int a_r = wm + ((lane >> 3) & 1) * 8 + (lane & 7);
    int a_cg = (lane >> 4);
    int b_r = wn + ((lane >> 4) & 1) * 8 + (lane & 7);
    int b_cg = ((lane >> 3) & 1);

    for (int i = 0; i < NCH; i++) {
        cp_wait<1>();
        __syncthreads();
        uint32_t st = sb + (uint32_t)(i % NSTAGE) * STAGE_BYTES;

        #pragma unroll
        for (int kt = 0; kt < 2; kt++) {
            uint32_t ah[2][4], al[2][4], bh[4][4], bl[4][4];
            #pragma unroll
            for (int mi = 0; mi < 2; mi++) {
                int r = a_r + mi * 16, c = 2 * kt + a_cg;
                LDSM4(ah[mi], st + A_HI + swz(r, c));
                LDSM4(al[mi], st + A_LO + swz(r, c));
            }
            #pragma unroll
            for (int bt = 0; bt < 4; bt++) {
                int r = b_r + bt * 16, c = 2 * kt + b_cg;
                LDSM4(bh[bt], st + B_HI + swz(r, c));
                LDSM4(bl[bt], st + B_LO + swz(r, c));
            }
            #pragma unroll
            for (int mi = 0; mi < 2; mi++)
                #pragma unroll
                for (int nf = 0; nf < 8; nf++) {
                    uint32_t bh0 = bh[nf >> 1][(nf & 1) * 2], bh1 = bh[nf >> 1][(nf & 1) * 2 + 1];
                    uint32_t bl0 = bl[nf >> 1][(nf & 1) * 2], bl1 = bl[nf >> 1][(nf & 1) * 2 + 1];
                    MMA(acc[mi][nf], ah[mi], bh0, bh1);
                    MMA(acc[mi][nf], ah[mi], bl0, bl1);
                    MMA(acc[mi][nf], al[mi], bh0, bh1);
                }
        }

        if (i + 2 < NCH)
            load_stage(sb + (uint32_t)((i + 2) % NSTAGE) * STAGE_BYTES,
                       tid, aHi, aLo, bHi, bLo, LDA, LDB, (i + 2) * BK);
        cp_commit();
        __syncthreads();
    }

    // epilogue
    #pragma unroll
    for (int mi = 0; mi < 2; mi++) {
        int m_base = row0 + wm + mi * 16 + (lane >> 2);
        #pragma unroll
        for (int half = 0; half < 2; half++) {
            size_t m = (size_t)(m_base + half * 8);
            #pragma unroll
            for (int nf = 0; nf < 8; nf++) {
                int n = n0 + wn + nf * 8 + (lane & 3) * 2;
                float v0 = acc[mi][nf][half * 2];
                float v1 = acc[mi][nf][half * 2 + 1];
                size_t off = m * ND + n;
                if (SPLIT_OUT) {
                    __nv_bfloat16 h0, l0, h1, l1;
                    split1(v0, h0, l0); split1(v1, h1, l1);
                    __nv_bfloat162 H; H.x = h0; H.y = h1;
                    __nv_bfloat162 L; L.x = l0; L.y = l1;
                    *(__nv_bfloat162*)(Chi + off) = H;
                    *(__nv_bfloat162*)(Clo + off) = L;
                } else {
                    if (accum) {
                        float2 old = *(float2*)(Cf + off);
                        v0 += old.x; v1 += old.y;
                    }
                    *(float2*)(Cf + off) = make_float2(v0, v1);
                }
            }
        }
    }
}

// gemm1: Hc[:, n0..] = A @ UP_e[:, n_base + n0 ..]   (KLEN = HID = 1024)
__global__ void __launch_bounds__(256, 1) k_gemm1(int expert, int n_base) {
    int tile = blockIdx.y;
    if (tile >= g_num_tiles || g_tile_expert[tile] != expert) return;
    int row0 = tile * BM, n0 = blockIdx.x * TILE_N;
    gemm_body<HID, HID, KCHUNK, true>(
        g_Ahi + (size_t)row0 * HID, g_Alo + (size_t)row0 * HID,
        g_W1hi + (size_t)(n_base + n0) * HID, g_W1lo + (size_t)(n_base + n0) * HID,
        g_Hchi, g_Hclo, nullptr, row0, n0, 0);
}

// gemm2: Y[:, n0..] (+)= Hc @ DN_e[k_base.., :]      (KLEN = KCHUNK = 1024)
__global__ void __launch_bounds__(256, 1) k_gemm2(int expert, int k_base, int accum) {
    int tile = blockIdx.y;
    if (tile >= g_num_tiles || g_tile_expert[tile] != expert) return;
    int row0 = tile * BM, n0 = blockIdx.x * TILE_N;
    gemm_body<KCHUNK, EXD, HID, false>(
        g_Hchi + (size_t)row0 * KCHUNK, g_Hclo + (size_t)row0 * KCHUNK,
        g_W2hi + (size_t)n0 * EXD + k_base, g_W2lo + (size_t)n0 * EXD + k_base,
        nullptr, nullptr, g_Y, row0, n0, accum);
}

// ---------------- combine ----------------
__global__ void k_combine(const float* __restrict__ ew, float* __restrict__ out) {
    int i = blockIdx.x * blockDim.x + threadIdx.x;
    if (i >= T_TOK * HID) return;
    int t = i >> 10, h = i & (HID - 1);
    int p0 = g_route_pos[t * TOPK + 0];
    int p1 = g_route_pos[t * TOPK + 1];
    float w0 = ew[t * TOPK + 0], w1 = ew[t * TOPK + 1];
    out[i] = w0 * g_Y[(size_t)p0 * HID + h] + w1 * g_Y[(size_t)p1 * HID + h];
}

// ---------------- launch ----------------
extern "C" void kernel_launch(void* const* d_in, const int* in_sizes, int n_in,
                              void* d_out, int out_size) {
    const float* x    = (const float*)d_in[0];
    const int*   idx  = (const int*)  d_in[1];
    const float* ew   = (const float*)d_in[2];
    const float* up   = (const float*)d_in[3];
    const float* down = (const float*)d_in[4];
    float* out = (float*)d_out;

    cudaFuncSetAttribute(k_gemm1, cudaFuncAttributeMaxDynamicSharedMemorySize, SMEM_BYTES);
    cudaFuncSetAttribute(k_gemm2, cudaFuncAttributeMaxDynamicSharedMemorySize, SMEM_BYTES);

    k_init   <<<(MAX_ROWS + 255) / 256, 256>>>();
    k_count  <<<(NROUTE + 255) / 256, 256>>>(idx);
    k_offsets<<<1, 32>>>();
    k_scatter<<<(NROUTE + 255) / 256, 256>>>(idx);
    k_convert_x<<<MAX_ROWS, 256>>>(x);

    for (int e = 0; e < NEXP; e++) {
        k_convert_w1<<<dim3(EXD / 32, HID / 32), dim3(32, 8)>>>(up   + (size_t)e * HID * EXD);
        k_convert_w2<<<dim3(HID / 32, EXD / 32), dim3(32, 8)>>>(down + (size_t)e * EXD * HID);
        for (int c = 0; c < EXD / KCHUNK; c++) {
            k_gemm1<<<dim3(KCHUNK / TILE_N, MAX_MT), 256, SMEM_BYTES>>>(e, c * KCHUNK);
            k_gemm2<<<dim3(HID / TILE_N, MAX_MT),   256, SMEM_BYTES>>>(e, c * KCHUNK, c > 0);
        }
    }

    k_combine<<<(T_TOK * HID + 255) / 256, 256>>>(ew, out);
}